// round 1
// baseline (speedup 1.0000x reference)
#include <cuda_runtime.h>

#define N_NODES 25000
#define E_EDGES 400000
#define HH 4
#define CC 256
#define D_IN 1024
#define D_OUT 1024   // H*C
#define NEG_SLOPE 0.2f

// ---------------- scratch (device globals: allocation-free) ----------------
__device__ float g_xp[(size_t)N_NODES * D_OUT];   // projected features [N, H*C]
__device__ float g_asrc[N_NODES * HH];
__device__ float g_adst[N_NODES * HH];
__device__ float g_m[N_NODES * HH];               // segment max
__device__ float g_z[N_NODES * HH];               // segment sum of exp
__device__ float g_ee[(size_t)E_EDGES * HH];      // per-edge exp(e - m[dst])
__device__ int   g_is64;                          // edge_index dtype flag

// ---------------- helpers ----------------
__device__ __forceinline__ int load_idx(const void* p, long long i) {
    if (g_is64) return (int)((const long long*)p)[i];
    return ((const int*)p)[i];
}

__device__ __forceinline__ void atomicMaxF(float* addr, float v) {
    int old = __float_as_int(*addr);
    while (__int_as_float(old) < v) {
        int assumed = old;
        old = atomicCAS((int*)addr, assumed, __float_as_int(v));
        if (old == assumed) break;
    }
}

__device__ __forceinline__ float leaky(float v) {
    return v > 0.0f ? v : NEG_SLOPE * v;
}

// ---------------- 0: probe edge_index dtype ----------------
// int64 nonneg values < 25000 => every high 32-bit word is 0.
// int32 random values in [0,25000) => odd slots almost surely nonzero.
__global__ void probe_kernel(const int* ei32) {
    if (threadIdx.x == 0 && blockIdx.x == 0) {
        int is64 = 1;
        for (int i = 0; i < 64; i++) {
            if (ei32[2 * i + 1] != 0) { is64 = 0; break; }
        }
        g_is64 = is64;
    }
}

// ---------------- 1: GEMM  xp = x @ W  (fp32, 128x128x8 tiles) ----------------
__global__ __launch_bounds__(256, 2)
void gemm_kernel(const float* __restrict__ A, const float* __restrict__ B) {
    __shared__ float As[8][128];
    __shared__ float Bs[8][128];

    const int tid = threadIdx.x;
    const int bx = blockIdx.x;     // 0..7 (col tile)
    const int by = blockIdx.y;     // 0..195 (row tile)
    const int tr = tid >> 4;       // 0..15
    const int tc = tid & 15;       // 0..15

    float acc[8][8];
#pragma unroll
    for (int i = 0; i < 8; i++)
#pragma unroll
        for (int j = 0; j < 8; j++) acc[i][j] = 0.0f;

    const int aRow = tid >> 1;          // 0..127
    const int aK   = (tid & 1) * 4;     // 0 or 4
    const int bRow = tid >> 5;          // 0..7
    const int bCol = (tid & 31) * 4;    // 0..124

    const long long gRowA = (long long)by * 128 + aRow;
    const bool aValid = gRowA < N_NODES;
    const float* Aptr = A + gRowA * D_IN + aK;
    const float* Bptr = B + (long long)bRow * D_OUT + (long long)bx * 128 + bCol;

    for (int k0 = 0; k0 < D_IN; k0 += 8) {
        float4 av = aValid ? *(const float4*)(Aptr + k0)
                           : make_float4(0.f, 0.f, 0.f, 0.f);
        As[aK + 0][aRow] = av.x;
        As[aK + 1][aRow] = av.y;
        As[aK + 2][aRow] = av.z;
        As[aK + 3][aRow] = av.w;
        float4 bv = *(const float4*)(Bptr + (long long)k0 * D_OUT);
        *(float4*)&Bs[bRow][bCol] = bv;
        __syncthreads();

#pragma unroll
        for (int kk = 0; kk < 8; kk++) {
            float a[8], b[8];
            *(float4*)(a)     = *(const float4*)&As[kk][tr * 8];
            *(float4*)(a + 4) = *(const float4*)&As[kk][tr * 8 + 4];
            *(float4*)(b)     = *(const float4*)&Bs[kk][tc * 8];
            *(float4*)(b + 4) = *(const float4*)&Bs[kk][tc * 8 + 4];
#pragma unroll
            for (int i = 0; i < 8; i++)
#pragma unroll
                for (int j = 0; j < 8; j++)
                    acc[i][j] = fmaf(a[i], b[j], acc[i][j]);
        }
        __syncthreads();
    }

#pragma unroll
    for (int i = 0; i < 8; i++) {
        long long row = (long long)by * 128 + tr * 8 + i;
        if (row < N_NODES) {
            float* crow = g_xp + row * D_OUT + (long long)bx * 128 + tc * 8;
            *(float4*)crow       = make_float4(acc[i][0], acc[i][1], acc[i][2], acc[i][3]);
            *(float4*)(crow + 4) = make_float4(acc[i][4], acc[i][5], acc[i][6], acc[i][7]);
        }
    }
}

// ---------------- 2: per-node attention logits + m init (self loop) ----------
__global__ void attn_kernel(const float* __restrict__ att_src,
                            const float* __restrict__ att_dst) {
    const int n = blockIdx.x;
    const int h = threadIdx.x >> 5;    // blockDim = 128 -> 4 warps
    const int lane = threadIdx.x & 31;
    const float* xrow = g_xp + (size_t)n * D_OUT + h * CC;
    const float* as = att_src + h * CC;
    const float* ad = att_dst + h * CC;
    float s1 = 0.f, s2 = 0.f;
#pragma unroll 4
    for (int c = lane; c < CC; c += 32) {
        float v = xrow[c];
        s1 = fmaf(v, as[c], s1);
        s2 = fmaf(v, ad[c], s2);
    }
#pragma unroll
    for (int o = 16; o; o >>= 1) {
        s1 += __shfl_xor_sync(0xffffffffu, s1, o);
        s2 += __shfl_xor_sync(0xffffffffu, s2, o);
    }
    if (lane == 0) {
        g_asrc[n * HH + h] = s1;
        g_adst[n * HH + h] = s2;
        g_m[n * HH + h] = leaky(s1 + s2);   // self-loop logit seeds the max
    }
}

// ---------------- 3: edge segment-max ----------------
__global__ void edge_max_kernel(const void* __restrict__ ei) {
    long long e = (long long)blockIdx.x * blockDim.x + threadIdx.x;
    if (e >= E_EDGES) return;
    int s = load_idx(ei, e);
    int d = load_idx(ei, E_EDGES + e);
#pragma unroll
    for (int h = 0; h < HH; h++) {
        float v = leaky(g_asrc[s * HH + h] + g_adst[d * HH + h]);
        atomicMaxF(&g_m[d * HH + h], v);
    }
}

// ---------------- 4: self-loop init of z and out ----------------
__global__ void self_init_kernel(float* __restrict__ out) {
    const int n = blockIdx.x;
    __shared__ float ee_sh[HH];
    if (threadIdx.x < HH) {
        int h = threadIdx.x;
        float e = leaky(g_asrc[n * HH + h] + g_adst[n * HH + h]);
        float ee = expf(e - g_m[n * HH + h]);
        g_z[n * HH + h] = ee;
        ee_sh[h] = ee;
    }
    __syncthreads();
    const float* xrow = g_xp + (size_t)n * D_OUT;
    float* orow = out + (size_t)n * D_OUT;
    for (int i = threadIdx.x; i < D_OUT; i += 256)
        orow[i] = ee_sh[i >> 8] * xrow[i];
}

// ---------------- 5: per-edge exp + z accumulation ----------------
__global__ void edge_ee_kernel(const void* __restrict__ ei) {
    long long e = (long long)blockIdx.x * blockDim.x + threadIdx.x;
    if (e >= E_EDGES) return;
    int s = load_idx(ei, e);
    int d = load_idx(ei, E_EDGES + e);
#pragma unroll
    for (int h = 0; h < HH; h++) {
        float v = leaky(g_asrc[s * HH + h] + g_adst[d * HH + h]);
        float ee = expf(v - g_m[d * HH + h]);
        g_ee[e * HH + h] = ee;
        atomicAdd(&g_z[d * HH + h], ee);
    }
}

// ---------------- 6: weighted scatter aggregation (warp per edge) ----------
__global__ __launch_bounds__(256)
void edge_agg_kernel(const void* __restrict__ ei, float* __restrict__ out) {
    long long w = ((long long)blockIdx.x * blockDim.x + threadIdx.x) >> 5;
    const int lane = threadIdx.x & 31;
    if (w >= E_EDGES) return;
    int s = load_idx(ei, w);
    int d = load_idx(ei, E_EDGES + w);
    float4 ee4 = *(const float4*)(g_ee + w * 4);
    const float* xs = g_xp + (size_t)s * D_OUT;
    float* od = out + (size_t)d * D_OUT;
#pragma unroll
    for (int h = 0; h < HH; h++) {
        float wgt = (h == 0) ? ee4.x : (h == 1) ? ee4.y : (h == 2) ? ee4.z : ee4.w;
#pragma unroll
        for (int j = 0; j < 2; j++) {
            int off = h * CC + j * 128 + lane * 4;
            float4 v = *(const float4*)(xs + off);
            asm volatile(
                "red.global.add.v4.f32 [%0], {%1, %2, %3, %4};"
                :: "l"(od + off),
                   "f"(v.x * wgt), "f"(v.y * wgt), "f"(v.z * wgt), "f"(v.w * wgt)
                : "memory");
        }
    }
}

// ---------------- 7: finalize: /z + bias + ReLU ----------------
__global__ void finalize_kernel(float* __restrict__ out,
                                const float* __restrict__ bias) {
    const int n = blockIdx.x;
    float* orow = out + (size_t)n * D_OUT;
    for (int i = threadIdx.x; i < D_OUT; i += 256) {
        float v = orow[i] / g_z[n * HH + (i >> 8)] + bias[i];
        orow[i] = v > 0.0f ? v : 0.0f;
    }
}

// ---------------- launch ----------------
extern "C" void kernel_launch(void* const* d_in, const int* in_sizes, int n_in,
                              void* d_out, int out_size) {
    const float* x        = (const float*)d_in[0];
    const void*  ei       = d_in[1];               // int32 or int64, probed
    const float* W        = (const float*)d_in[2];
    const float* att_src  = (const float*)d_in[3];
    const float* att_dst  = (const float*)d_in[4];
    const float* bias     = (const float*)d_in[5];
    float* out = (float*)d_out;

    probe_kernel<<<1, 32>>>((const int*)ei);

    dim3 ggrid(D_OUT / 128, (N_NODES + 127) / 128);
    gemm_kernel<<<ggrid, 256>>>(x, W);

    attn_kernel<<<N_NODES, 128>>>(att_src, att_dst);

    int eb = (E_EDGES + 255) / 256;
    edge_max_kernel<<<eb, 256>>>(ei);

    self_init_kernel<<<N_NODES, 256>>>(out);

    edge_ee_kernel<<<eb, 256>>>(ei);

    long long agg_threads = (long long)E_EDGES * 32;
    int agg_blocks = (int)((agg_threads + 255) / 256);
    edge_agg_kernel<<<agg_blocks, 256>>>(ei, out);

    finalize_kernel<<<N_NODES, 256>>>(out, bias);
}

// round 2
// speedup vs baseline: 1.7980x; 1.7980x over previous
#include <cuda_runtime.h>
#include <cstdint>

#define N_NODES 25000
#define E_EDGES 400000
#define HH 4
#define CC 256
#define D_IN 1024
#define D_OUT 1024   // H*C
#define NEG_SLOPE 0.2f

// ---------------- scratch (device globals: allocation-free) ----------------
__device__ float g_xp[(size_t)N_NODES * D_OUT];   // projected features [N, H*C]
__device__ float g_asrc[N_NODES * HH];
__device__ float g_adst[N_NODES * HH];
__device__ float g_m[N_NODES * HH];               // segment max
__device__ float g_z[N_NODES * HH];               // segment sum of exp
__device__ float g_ee[(size_t)E_EDGES * HH];      // per-edge exp(e - m[dst])
__device__ int   g_is64;                          // edge_index dtype flag

// ---------------- helpers ----------------
__device__ __forceinline__ int load_idx(const void* p, long long i) {
    if (g_is64) return (int)((const long long*)p)[i];
    return ((const int*)p)[i];
}

__device__ __forceinline__ void atomicMaxF(float* addr, float v) {
    int old = __float_as_int(*addr);
    while (__int_as_float(old) < v) {
        int assumed = old;
        old = atomicCAS((int*)addr, assumed, __float_as_int(v));
        if (old == assumed) break;
    }
}

__device__ __forceinline__ float leaky(float v) {
    return v > 0.0f ? v : NEG_SLOPE * v;
}

__device__ __forceinline__ uint32_t f2tf(float f) {
    uint32_t r;
    asm("cvt.rna.tf32.f32 %0, %1;" : "=r"(r) : "f"(f));
    return r;
}

__device__ __forceinline__ void mma_tf32(float* d, const uint32_t* a, const uint32_t* b) {
    asm volatile(
        "mma.sync.aligned.m16n8k8.row.col.f32.tf32.tf32.f32 "
        "{%0,%1,%2,%3}, {%4,%5,%6,%7}, {%8,%9}, {%0,%1,%2,%3};"
        : "+f"(d[0]), "+f"(d[1]), "+f"(d[2]), "+f"(d[3])
        : "r"(a[0]), "r"(a[1]), "r"(a[2]), "r"(a[3]), "r"(b[0]), "r"(b[1]));
}

// ---------------- 0: probe edge_index dtype ----------------
__global__ void probe_kernel(const int* ei32) {
    if (threadIdx.x == 0 && blockIdx.x == 0) {
        int is64 = 1;
        for (int i = 0; i < 64; i++) {
            if (ei32[2 * i + 1] != 0) { is64 = 0; break; }
        }
        g_is64 = is64;
    }
}

// ---------------- 1: GEMM xp = x @ W  (tf32 tensor-core, 128x128x16) --------
// 256 threads = 8 warps (2x4). Warp tile 64x32 via m16n8k8 tf32 mma.
// Smem stride 136 words: (136*k + m) % 32 == (8k + m) % 32 -> all fragment
// loads conflict-free. Double-buffered with register staging.
#define SA 136
__global__ __launch_bounds__(256)
void gemm_tf32_kernel(const float* __restrict__ A, const float* __restrict__ B) {
    __shared__ uint32_t As[2][16 * SA];
    __shared__ uint32_t Bs[2][16 * SA];

    const int tid  = threadIdx.x;
    const int lane = tid & 31;
    const int wid  = tid >> 5;
    const int wm   = wid >> 2;      // 0..1
    const int wn   = wid & 3;       // 0..3
    const int lm   = lane >> 2;     // 0..7
    const int lk   = lane & 3;      // 0..3

    const int gm0 = blockIdx.y * 128;
    const int bn0 = blockIdx.x * 128;

    // A staging: thread -> row tid>>1 (0..127), k-half (tid&1)*8; 2x float4
    const int arow  = tid >> 1;
    const int akoff = (tid & 1) * 8;
    int grow = gm0 + arow;
    if (grow >= N_NODES) grow = N_NODES - 1;   // clamp; garbage rows discarded
    const float* aptr = A + (size_t)grow * D_IN + akoff;

    // B staging: thread -> k-row tid>>4 (0..15), col4 (tid&15)*4; 2x float4
    const int bkr = tid >> 4;
    const int bcc = (tid & 15) * 4;
    const float* bptr = B + (size_t)bkr * D_OUT + bn0 + bcc;

    float acc[4][4][4];
#pragma unroll
    for (int i = 0; i < 4; i++)
#pragma unroll
        for (int j = 0; j < 4; j++)
#pragma unroll
            for (int r = 0; r < 4; r++) acc[i][j][r] = 0.0f;

    float4 av0, av1, bv0, bv1;

    // ---- prologue: tile 0 ----
    av0 = *(const float4*)(aptr);
    av1 = *(const float4*)(aptr + 4);
    bv0 = *(const float4*)(bptr);
    bv1 = *(const float4*)(bptr + 64);
    {
        uint32_t* as = As[0];
        as[(akoff + 0) * SA + arow] = f2tf(av0.x);
        as[(akoff + 1) * SA + arow] = f2tf(av0.y);
        as[(akoff + 2) * SA + arow] = f2tf(av0.z);
        as[(akoff + 3) * SA + arow] = f2tf(av0.w);
        as[(akoff + 4) * SA + arow] = f2tf(av1.x);
        as[(akoff + 5) * SA + arow] = f2tf(av1.y);
        as[(akoff + 6) * SA + arow] = f2tf(av1.z);
        as[(akoff + 7) * SA + arow] = f2tf(av1.w);
        uint32_t* bs = Bs[0];
        uint4 p0 = make_uint4(f2tf(bv0.x), f2tf(bv0.y), f2tf(bv0.z), f2tf(bv0.w));
        uint4 p1 = make_uint4(f2tf(bv1.x), f2tf(bv1.y), f2tf(bv1.z), f2tf(bv1.w));
        *(uint4*)&bs[bkr * SA + bcc]      = p0;
        *(uint4*)&bs[bkr * SA + bcc + 64] = p1;
    }
    __syncthreads();

    const int NT = D_IN / 16;   // 64 k-tiles
    for (int t = 0; t < NT; t++) {
        if (t + 1 < NT) {
            const int k0 = (t + 1) * 16;
            av0 = *(const float4*)(aptr + k0);
            av1 = *(const float4*)(aptr + k0 + 4);
            bv0 = *(const float4*)(bptr + (size_t)k0 * D_OUT);
            bv1 = *(const float4*)(bptr + (size_t)k0 * D_OUT + 64);
        }

        const uint32_t* as = As[t & 1];
        const uint32_t* bs = Bs[t & 1];
#pragma unroll
        for (int ks = 0; ks < 2; ks++) {
            const int kb = ks * 8;
            uint32_t af[4][4], bf[4][2];
#pragma unroll
            for (int mi = 0; mi < 4; mi++) {
                int r = wm * 64 + mi * 16 + lm;
                af[mi][0] = as[(kb + lk) * SA + r];
                af[mi][1] = as[(kb + lk) * SA + r + 8];
                af[mi][2] = as[(kb + lk + 4) * SA + r];
                af[mi][3] = as[(kb + lk + 4) * SA + r + 8];
            }
#pragma unroll
            for (int ni = 0; ni < 4; ni++) {
                int c = wn * 32 + ni * 8 + lm;
                bf[ni][0] = bs[(kb + lk) * SA + c];
                bf[ni][1] = bs[(kb + lk + 4) * SA + c];
            }
#pragma unroll
            for (int mi = 0; mi < 4; mi++)
#pragma unroll
                for (int ni = 0; ni < 4; ni++)
                    mma_tf32(acc[mi][ni], af[mi], bf[ni]);
        }

        if (t + 1 < NT) {
            uint32_t* asw = As[(t + 1) & 1];
            asw[(akoff + 0) * SA + arow] = f2tf(av0.x);
            asw[(akoff + 1) * SA + arow] = f2tf(av0.y);
            asw[(akoff + 2) * SA + arow] = f2tf(av0.z);
            asw[(akoff + 3) * SA + arow] = f2tf(av0.w);
            asw[(akoff + 4) * SA + arow] = f2tf(av1.x);
            asw[(akoff + 5) * SA + arow] = f2tf(av1.y);
            asw[(akoff + 6) * SA + arow] = f2tf(av1.z);
            asw[(akoff + 7) * SA + arow] = f2tf(av1.w);
            uint32_t* bsw = Bs[(t + 1) & 1];
            uint4 p0 = make_uint4(f2tf(bv0.x), f2tf(bv0.y), f2tf(bv0.z), f2tf(bv0.w));
            uint4 p1 = make_uint4(f2tf(bv1.x), f2tf(bv1.y), f2tf(bv1.z), f2tf(bv1.w));
            *(uint4*)&bsw[bkr * SA + bcc]      = p0;
            *(uint4*)&bsw[bkr * SA + bcc + 64] = p1;
        }
        __syncthreads();
    }

    // ---- epilogue ----
#pragma unroll
    for (int mi = 0; mi < 4; mi++) {
        int row0 = gm0 + wm * 64 + mi * 16 + lm;
#pragma unroll
        for (int ni = 0; ni < 4; ni++) {
            int col = bn0 + wn * 32 + ni * 8 + lk * 2;
            if (row0 < N_NODES)
                *(float2*)&g_xp[(size_t)row0 * D_OUT + col] =
                    make_float2(acc[mi][ni][0], acc[mi][ni][1]);
            if (row0 + 8 < N_NODES)
                *(float2*)&g_xp[(size_t)(row0 + 8) * D_OUT + col] =
                    make_float2(acc[mi][ni][2], acc[mi][ni][3]);
        }
    }
}

// ---------------- 2: per-node attention logits + m init (self loop) ----------
__global__ void attn_kernel(const float* __restrict__ att_src,
                            const float* __restrict__ att_dst) {
    const int n = blockIdx.x;
    const int h = threadIdx.x >> 5;
    const int lane = threadIdx.x & 31;
    const float* xrow = g_xp + (size_t)n * D_OUT + h * CC;
    const float* as = att_src + h * CC;
    const float* ad = att_dst + h * CC;
    float s1 = 0.f, s2 = 0.f;
#pragma unroll 4
    for (int c = lane; c < CC; c += 32) {
        float v = xrow[c];
        s1 = fmaf(v, as[c], s1);
        s2 = fmaf(v, ad[c], s2);
    }
#pragma unroll
    for (int o = 16; o; o >>= 1) {
        s1 += __shfl_xor_sync(0xffffffffu, s1, o);
        s2 += __shfl_xor_sync(0xffffffffu, s2, o);
    }
    if (lane == 0) {
        g_asrc[n * HH + h] = s1;
        g_adst[n * HH + h] = s2;
        g_m[n * HH + h] = leaky(s1 + s2);
    }
}

// ---------------- 3: edge segment-max ----------------
__global__ void edge_max_kernel(const void* __restrict__ ei) {
    long long e = (long long)blockIdx.x * blockDim.x + threadIdx.x;
    if (e >= E_EDGES) return;
    int s = load_idx(ei, e);
    int d = load_idx(ei, E_EDGES + e);
#pragma unroll
    for (int h = 0; h < HH; h++) {
        float v = leaky(g_asrc[s * HH + h] + g_adst[d * HH + h]);
        atomicMaxF(&g_m[d * HH + h], v);
    }
}

// ---------------- 4: self-loop init of z and out ----------------
__global__ void self_init_kernel(float* __restrict__ out) {
    const int n = blockIdx.x;
    __shared__ float ee_sh[HH];
    if (threadIdx.x < HH) {
        int h = threadIdx.x;
        float e = leaky(g_asrc[n * HH + h] + g_adst[n * HH + h]);
        float ee = expf(e - g_m[n * HH + h]);
        g_z[n * HH + h] = ee;
        ee_sh[h] = ee;
    }
    __syncthreads();
    const float* xrow = g_xp + (size_t)n * D_OUT;
    float* orow = out + (size_t)n * D_OUT;
    for (int i = threadIdx.x; i < D_OUT; i += 256)
        orow[i] = ee_sh[i >> 8] * xrow[i];
}

// ---------------- 5: per-edge exp + z accumulation ----------------
__global__ void edge_ee_kernel(const void* __restrict__ ei) {
    long long e = (long long)blockIdx.x * blockDim.x + threadIdx.x;
    if (e >= E_EDGES) return;
    int s = load_idx(ei, e);
    int d = load_idx(ei, E_EDGES + e);
#pragma unroll
    for (int h = 0; h < HH; h++) {
        float v = leaky(g_asrc[s * HH + h] + g_adst[d * HH + h]);
        float ee = expf(v - g_m[d * HH + h]);
        g_ee[e * HH + h] = ee;
        atomicAdd(&g_z[d * HH + h], ee);
    }
}

// ---------------- 6: weighted scatter aggregation (warp per edge) ----------
__global__ __launch_bounds__(256)
void edge_agg_kernel(const void* __restrict__ ei, float* __restrict__ out) {
    long long w = ((long long)blockIdx.x * blockDim.x + threadIdx.x) >> 5;
    const int lane = threadIdx.x & 31;
    if (w >= E_EDGES) return;
    int s = load_idx(ei, w);
    int d = load_idx(ei, E_EDGES + w);
    float4 ee4 = *(const float4*)(g_ee + w * 4);
    const float* xs = g_xp + (size_t)s * D_OUT;
    float* od = out + (size_t)d * D_OUT;
#pragma unroll
    for (int h = 0; h < HH; h++) {
        float wgt = (h == 0) ? ee4.x : (h == 1) ? ee4.y : (h == 2) ? ee4.z : ee4.w;
#pragma unroll
        for (int j = 0; j < 2; j++) {
            int off = h * CC + j * 128 + lane * 4;
            float4 v = *(const float4*)(xs + off);
            asm volatile(
                "red.global.add.v4.f32 [%0], {%1, %2, %3, %4};"
                :: "l"(od + off),
                   "f"(v.x * wgt), "f"(v.y * wgt), "f"(v.z * wgt), "f"(v.w * wgt)
                : "memory");
        }
    }
}

// ---------------- 7: finalize: /z + bias + ReLU ----------------
__global__ void finalize_kernel(float* __restrict__ out,
                                const float* __restrict__ bias) {
    const int n = blockIdx.x;
    float* orow = out + (size_t)n * D_OUT;
    for (int i = threadIdx.x; i < D_OUT; i += 256) {
        float v = orow[i] / g_z[n * HH + (i >> 8)] + bias[i];
        orow[i] = v > 0.0f ? v : 0.0f;
    }
}

// ---------------- launch ----------------
extern "C" void kernel_launch(void* const* d_in, const int* in_sizes, int n_in,
                              void* d_out, int out_size) {
    const float* x        = (const float*)d_in[0];
    const void*  ei       = d_in[1];
    const float* W        = (const float*)d_in[2];
    const float* att_src  = (const float*)d_in[3];
    const float* att_dst  = (const float*)d_in[4];
    const float* bias     = (const float*)d_in[5];
    float* out = (float*)d_out;

    probe_kernel<<<1, 32>>>((const int*)ei);

    dim3 ggrid(D_OUT / 128, (N_NODES + 127) / 128);
    gemm_tf32_kernel<<<ggrid, 256>>>(x, W);

    attn_kernel<<<N_NODES, 128>>>(att_src, att_dst);

    int eb = (E_EDGES + 255) / 256;
    edge_max_kernel<<<eb, 256>>>(ei);

    self_init_kernel<<<N_NODES, 256>>>(out);

    edge_ee_kernel<<<eb, 256>>>(ei);

    long long agg_threads = (long long)E_EDGES * 32;
    int agg_blocks = (int)((agg_threads + 255) / 256);
    edge_agg_kernel<<<agg_blocks, 256>>>(ei, out);

    finalize_kernel<<<N_NODES, 256>>>(out, bias);
}

// round 5
// speedup vs baseline: 2.7823x; 1.5474x over previous
#include <cuda_runtime.h>
#include <cstdint>

#define N_NODES 25000
#define E_EDGES 400000
#define HH 4
#define CC 256
#define D_IN 1024
#define D_OUT 1024   // H*C
#define NEG_SLOPE 0.2f

// ---------------- scratch (device globals: allocation-free) ----------------
__device__ float g_xp[(size_t)N_NODES * D_OUT];   // projected features [N, H*C]
__device__ float g_asrc[N_NODES * HH];
__device__ float g_adst[N_NODES * HH];
__device__ float g_z[N_NODES * HH];               // softmax denominator
__device__ float g_eself[N_NODES * HH];           // exp of self-loop logit
__device__ float g_alpha[(size_t)E_EDGES * HH];   // per-edge ee, CSR order
__device__ int   g_csr_src[E_EDGES];              // src ids, CSR-by-dst
__device__ int   g_cnt[N_NODES];
__device__ int   g_rowptr[N_NODES + 1];
__device__ int   g_cursor[N_NODES];
__device__ int   g_is64;

// ---------------- helpers ----------------
__device__ __forceinline__ int load_idx(const void* p, long long i) {
    if (g_is64) return (int)((const long long*)p)[i];
    return ((const int*)p)[i];
}

__device__ __forceinline__ float leaky(float v) {
    return v > 0.0f ? v : NEG_SLOPE * v;
}

__device__ __forceinline__ uint32_t f2tf(float f) {
    uint32_t r;
    asm("cvt.rna.tf32.f32 %0, %1;" : "=r"(r) : "f"(f));
    return r;
}

__device__ __forceinline__ void mma_tf32(float* d, const uint32_t* a, const uint32_t* b) {
    asm volatile(
        "mma.sync.aligned.m16n8k8.row.col.f32.tf32.tf32.f32 "
        "{%0,%1,%2,%3}, {%4,%5,%6,%7}, {%8,%9}, {%0,%1,%2,%3};"
        : "+f"(d[0]), "+f"(d[1]), "+f"(d[2]), "+f"(d[3])
        : "r"(a[0]), "r"(a[1]), "r"(a[2]), "r"(a[3]), "r"(b[0]), "r"(b[1]));
}

// ---------------- 0: probe edge_index dtype ----------------
__global__ void probe_kernel(const int* ei32) {
    if (threadIdx.x == 0 && blockIdx.x == 0) {
        int is64 = 1;
        for (int i = 0; i < 64; i++) {
            if (ei32[2 * i + 1] != 0) { is64 = 0; break; }
        }
        g_is64 = is64;
    }
}

// ---------------- 1: GEMM xp = x @ W  (tf32 tensor-core, 128x128x16) --------
#define SA 136
__global__ __launch_bounds__(256)
void gemm_tf32_kernel(const float* __restrict__ A, const float* __restrict__ B) {
    __shared__ uint32_t As[2][16 * SA];
    __shared__ uint32_t Bs[2][16 * SA];

    const int tid  = threadIdx.x;
    const int lane = tid & 31;
    const int wid  = tid >> 5;
    const int wm   = wid >> 2;
    const int wn   = wid & 3;
    const int lm   = lane >> 2;
    const int lk   = lane & 3;

    const int gm0 = blockIdx.y * 128;
    const int bn0 = blockIdx.x * 128;

    const int arow  = tid >> 1;
    const int akoff = (tid & 1) * 8;
    int grow = gm0 + arow;
    if (grow >= N_NODES) grow = N_NODES - 1;
    const float* aptr = A + (size_t)grow * D_IN + akoff;

    const int bkr = tid >> 4;
    const int bcc = (tid & 15) * 4;
    const float* bptr = B + (size_t)bkr * D_OUT + bn0 + bcc;

    float acc[4][4][4];
#pragma unroll
    for (int i = 0; i < 4; i++)
#pragma unroll
        for (int j = 0; j < 4; j++)
#pragma unroll
            for (int r = 0; r < 4; r++) acc[i][j][r] = 0.0f;

    float4 av0, av1, bv0, bv1;

    av0 = *(const float4*)(aptr);
    av1 = *(const float4*)(aptr + 4);
    bv0 = *(const float4*)(bptr);
    bv1 = *(const float4*)(bptr + 64);
    {
        uint32_t* as = As[0];
        as[(akoff + 0) * SA + arow] = f2tf(av0.x);
        as[(akoff + 1) * SA + arow] = f2tf(av0.y);
        as[(akoff + 2) * SA + arow] = f2tf(av0.z);
        as[(akoff + 3) * SA + arow] = f2tf(av0.w);
        as[(akoff + 4) * SA + arow] = f2tf(av1.x);
        as[(akoff + 5) * SA + arow] = f2tf(av1.y);
        as[(akoff + 6) * SA + arow] = f2tf(av1.z);
        as[(akoff + 7) * SA + arow] = f2tf(av1.w);
        uint32_t* bs = Bs[0];
        uint4 p0 = make_uint4(f2tf(bv0.x), f2tf(bv0.y), f2tf(bv0.z), f2tf(bv0.w));
        uint4 p1 = make_uint4(f2tf(bv1.x), f2tf(bv1.y), f2tf(bv1.z), f2tf(bv1.w));
        *(uint4*)&bs[bkr * SA + bcc]      = p0;
        *(uint4*)&bs[bkr * SA + bcc + 64] = p1;
    }
    __syncthreads();

    const int NT = D_IN / 16;
    for (int t = 0; t < NT; t++) {
        if (t + 1 < NT) {
            const int k0 = (t + 1) * 16;
            av0 = *(const float4*)(aptr + k0);
            av1 = *(const float4*)(aptr + k0 + 4);
            bv0 = *(const float4*)(bptr + (size_t)k0 * D_OUT);
            bv1 = *(const float4*)(bptr + (size_t)k0 * D_OUT + 64);
        }

        const uint32_t* as = As[t & 1];
        const uint32_t* bs = Bs[t & 1];
#pragma unroll
        for (int ks = 0; ks < 2; ks++) {
            const int kb = ks * 8;
            uint32_t af[4][4], bf[4][2];
#pragma unroll
            for (int mi = 0; mi < 4; mi++) {
                int r = wm * 64 + mi * 16 + lm;
                af[mi][0] = as[(kb + lk) * SA + r];
                af[mi][1] = as[(kb + lk) * SA + r + 8];
                af[mi][2] = as[(kb + lk + 4) * SA + r];
                af[mi][3] = as[(kb + lk + 4) * SA + r + 8];
            }
#pragma unroll
            for (int ni = 0; ni < 4; ni++) {
                int c = wn * 32 + ni * 8 + lm;
                bf[ni][0] = bs[(kb + lk) * SA + c];
                bf[ni][1] = bs[(kb + lk + 4) * SA + c];
            }
#pragma unroll
            for (int mi = 0; mi < 4; mi++)
#pragma unroll
                for (int ni = 0; ni < 4; ni++)
                    mma_tf32(acc[mi][ni], af[mi], bf[ni]);
        }

        if (t + 1 < NT) {
            uint32_t* asw = As[(t + 1) & 1];
            asw[(akoff + 0) * SA + arow] = f2tf(av0.x);
            asw[(akoff + 1) * SA + arow] = f2tf(av0.y);
            asw[(akoff + 2) * SA + arow] = f2tf(av0.z);
            asw[(akoff + 3) * SA + arow] = f2tf(av0.w);
            asw[(akoff + 4) * SA + arow] = f2tf(av1.x);
            asw[(akoff + 5) * SA + arow] = f2tf(av1.y);
            asw[(akoff + 6) * SA + arow] = f2tf(av1.z);
            asw[(akoff + 7) * SA + arow] = f2tf(av1.w);
            uint32_t* bsw = Bs[(t + 1) & 1];
            uint4 p0 = make_uint4(f2tf(bv0.x), f2tf(bv0.y), f2tf(bv0.z), f2tf(bv0.w));
            uint4 p1 = make_uint4(f2tf(bv1.x), f2tf(bv1.y), f2tf(bv1.z), f2tf(bv1.w));
            *(uint4*)&bsw[bkr * SA + bcc]      = p0;
            *(uint4*)&bsw[bkr * SA + bcc + 64] = p1;
        }
        __syncthreads();
    }

#pragma unroll
    for (int mi = 0; mi < 4; mi++) {
        int row0 = gm0 + wm * 64 + mi * 16 + lm;
#pragma unroll
        for (int ni = 0; ni < 4; ni++) {
            int col = bn0 + wn * 32 + ni * 8 + lk * 2;
            if (row0 < N_NODES)
                *(float2*)&g_xp[(size_t)row0 * D_OUT + col] =
                    make_float2(acc[mi][ni][0], acc[mi][ni][1]);
            if (row0 + 8 < N_NODES)
                *(float2*)&g_xp[(size_t)(row0 + 8) * D_OUT + col] =
                    make_float2(acc[mi][ni][2], acc[mi][ni][3]);
        }
    }
}

// ---------------- 2: per-node attention logits ----------------
__global__ void attn_kernel(const float* __restrict__ att_src,
                            const float* __restrict__ att_dst) {
    const int n = blockIdx.x;
    const int h = threadIdx.x >> 5;
    const int lane = threadIdx.x & 31;
    const float* xrow = g_xp + (size_t)n * D_OUT + h * CC;
    const float* as = att_src + h * CC;
    const float* ad = att_dst + h * CC;
    float s1 = 0.f, s2 = 0.f;
#pragma unroll 4
    for (int c = lane; c < CC; c += 32) {
        float v = xrow[c];
        s1 = fmaf(v, as[c], s1);
        s2 = fmaf(v, ad[c], s2);
    }
#pragma unroll
    for (int o = 16; o; o >>= 1) {
        s1 += __shfl_xor_sync(0xffffffffu, s1, o);
        s2 += __shfl_xor_sync(0xffffffffu, s2, o);
    }
    if (lane == 0) {
        g_asrc[n * HH + h] = s1;
        g_adst[n * HH + h] = s2;
    }
}

// ---------------- 3: CSR build ----------------
__global__ void zero_cnt_kernel() {
    int i = blockIdx.x * 256 + threadIdx.x;
    if (i < N_NODES) g_cnt[i] = 0;
}

__global__ void hist_kernel(const void* __restrict__ ei) {
    long long e = (long long)blockIdx.x * blockDim.x + threadIdx.x;
    if (e >= E_EDGES) return;
    atomicAdd(&g_cnt[load_idx(ei, E_EDGES + e)], 1);
}

__global__ void scan_kernel() {   // single block, 1024 threads
    __shared__ int part[1024];
    const int tid = threadIdx.x;
    const int CH = (N_NODES + 1023) / 1024;   // 25
    const int base = tid * CH;
    int s = 0;
    for (int i = 0; i < CH; i++) {
        int idx = base + i;
        if (idx < N_NODES) s += g_cnt[idx];
    }
    part[tid] = s;
    __syncthreads();
    for (int o = 1; o < 1024; o <<= 1) {
        int v = 0;
        if (tid >= o) v = part[tid - o];
        __syncthreads();
        if (tid >= o) part[tid] += v;
        __syncthreads();
    }
    int run = (tid == 0) ? 0 : part[tid - 1];
    for (int i = 0; i < CH; i++) {
        int idx = base + i;
        if (idx < N_NODES) {
            g_rowptr[idx] = run;
            g_cursor[idx] = run;
            run += g_cnt[idx];
        }
    }
    if (tid == 1023) g_rowptr[N_NODES] = E_EDGES;
}

__global__ void scatter_kernel(const void* __restrict__ ei) {
    long long e = (long long)blockIdx.x * blockDim.x + threadIdx.x;
    if (e >= E_EDGES) return;
    int s = load_idx(ei, e);
    int d = load_idx(ei, E_EDGES + e);
    int pos = atomicAdd(&g_cursor[d], 1);
    g_csr_src[pos] = s;
}

// ---------------- 4: per-dst softmax scalars ----------------
__global__ void softmax_kernel() {
    int d = blockIdx.x * 256 + threadIdx.x;
    if (d >= N_NODES) return;
    float4 ad = *(const float4*)&g_adst[d * HH];
    float4 sf = *(const float4*)&g_asrc[d * HH];
    float m0 = leaky(sf.x + ad.x), m1 = leaky(sf.y + ad.y);
    float m2 = leaky(sf.z + ad.z), m3 = leaky(sf.w + ad.w);
    const int beg = g_rowptr[d], end = g_rowptr[d + 1];
    for (int j = beg; j < end; j++) {
        int s = g_csr_src[j];
        float4 as = *(const float4*)&g_asrc[s * HH];
        m0 = fmaxf(m0, leaky(as.x + ad.x));
        m1 = fmaxf(m1, leaky(as.y + ad.y));
        m2 = fmaxf(m2, leaky(as.z + ad.z));
        m3 = fmaxf(m3, leaky(as.w + ad.w));
    }
    float z0 = expf(leaky(sf.x + ad.x) - m0);
    float z1 = expf(leaky(sf.y + ad.y) - m1);
    float z2 = expf(leaky(sf.z + ad.z) - m2);
    float z3 = expf(leaky(sf.w + ad.w) - m3);
    *(float4*)&g_eself[d * HH] = make_float4(z0, z1, z2, z3);
    for (int j = beg; j < end; j++) {
        int s = g_csr_src[j];
        float4 as = *(const float4*)&g_asrc[s * HH];
        float e0 = expf(leaky(as.x + ad.x) - m0);
        float e1 = expf(leaky(as.y + ad.y) - m1);
        float e2 = expf(leaky(as.z + ad.z) - m2);
        float e3 = expf(leaky(as.w + ad.w) - m3);
        *(float4*)&g_alpha[(size_t)j * HH] = make_float4(e0, e1, e2, e3);
        z0 += e0; z1 += e1; z2 += e2; z3 += e3;
    }
    *(float4*)&g_z[d * HH] = make_float4(z0, z1, z2, z3);
}

// ---------------- 5: warp-per-dst gather aggregation (+bias+ReLU) ----------
// Each lane owns 8 float4 chunks of the 1024-float row; head of chunk q is q>>1.
__global__ __launch_bounds__(256)
void agg_kernel(float* __restrict__ out, const float* __restrict__ bias) {
    const int d = blockIdx.x * 8 + (threadIdx.x >> 5);
    const int lane = threadIdx.x & 31;
    if (d >= N_NODES) return;

    float4 es = *(const float4*)&g_eself[d * HH];
    float wh[4] = {es.x, es.y, es.z, es.w};

    float4 acc[8];
    const float* xd = g_xp + (size_t)d * D_OUT;
#pragma unroll
    for (int q = 0; q < 8; q++) {
        const int off = q * 128 + lane * 4;
        float4 v = *(const float4*)(xd + off);
        float w = wh[q >> 1];
        acc[q] = make_float4(v.x * w, v.y * w, v.z * w, v.w * w);
    }

    const int beg = g_rowptr[d], end = g_rowptr[d + 1];
    for (int j = beg; j < end; j++) {
        int s = g_csr_src[j];
        float4 a4 = *(const float4*)&g_alpha[(size_t)j * HH];
        float aw[4] = {a4.x, a4.y, a4.z, a4.w};
        const float* xs = g_xp + (size_t)s * D_OUT;
#pragma unroll
        for (int q = 0; q < 8; q++) {
            const int off = q * 128 + lane * 4;
            float4 v = *(const float4*)(xs + off);
            float w = aw[q >> 1];
            acc[q].x = fmaf(v.x, w, acc[q].x);
            acc[q].y = fmaf(v.y, w, acc[q].y);
            acc[q].z = fmaf(v.z, w, acc[q].z);
            acc[q].w = fmaf(v.w, w, acc[q].w);
        }
    }

    float4 z4 = *(const float4*)&g_z[d * HH];
    float rz[4] = {1.0f / z4.x, 1.0f / z4.y, 1.0f / z4.z, 1.0f / z4.w};
    float* orow = out + (size_t)d * D_OUT;
#pragma unroll
    for (int q = 0; q < 8; q++) {
        const int off = q * 128 + lane * 4;
        float4 b4 = *(const float4*)(bias + off);
        float r = rz[q >> 1];
        float4 o;
        o.x = fmaf(acc[q].x, r, b4.x);
        o.y = fmaf(acc[q].y, r, b4.y);
        o.z = fmaf(acc[q].z, r, b4.z);
        o.w = fmaf(acc[q].w, r, b4.w);
        o.x = o.x > 0.f ? o.x : 0.f;
        o.y = o.y > 0.f ? o.y : 0.f;
        o.z = o.z > 0.f ? o.z : 0.f;
        o.w = o.w > 0.f ? o.w : 0.f;
        *(float4*)(orow + off) = o;
    }
}

// ---------------- launch ----------------
extern "C" void kernel_launch(void* const* d_in, const int* in_sizes, int n_in,
                              void* d_out, int out_size) {
    const float* x        = (const float*)d_in[0];
    const void*  ei       = d_in[1];
    const float* W        = (const float*)d_in[2];
    const float* att_src  = (const float*)d_in[3];
    const float* att_dst  = (const float*)d_in[4];
    const float* bias     = (const float*)d_in[5];
    float* out = (float*)d_out;

    probe_kernel<<<1, 32>>>((const int*)ei);

    // CSR build (independent of GEMM)
    zero_cnt_kernel<<<(N_NODES + 255) / 256, 256>>>();
    int eb = (E_EDGES + 255) / 256;
    hist_kernel<<<eb, 256>>>(ei);
    scan_kernel<<<1, 1024>>>();
    scatter_kernel<<<eb, 256>>>(ei);

    dim3 ggrid(D_OUT / 128, (N_NODES + 127) / 128);
    gemm_tf32_kernel<<<ggrid, 256>>>(x, W);

    attn_kernel<<<N_NODES, 128>>>(att_src, att_dst);

    softmax_kernel<<<(N_NODES + 255) / 256, 256>>>();

    agg_kernel<<<(N_NODES + 7) / 8, 256>>>(out, bias);
}

// round 6
// speedup vs baseline: 3.0990x; 1.1138x over previous
#include <cuda_runtime.h>
#include <cstdint>

#define N_NODES 25000
#define E_EDGES 400000
#define HH 4
#define CC 256
#define D_IN 1024
#define D_OUT 1024   // H*C
#define NEG_SLOPE 0.2f

// ---------------- scratch (device globals: allocation-free) ----------------
__device__ float g_xp[(size_t)N_NODES * D_OUT];   // projected features [N, H*C]
__device__ float g_asrc[N_NODES * HH];
__device__ float g_adst[N_NODES * HH];
__device__ float g_z[N_NODES * HH];               // softmax denominator
__device__ float g_eself[N_NODES * HH];           // exp of self-loop logit
__device__ float g_alpha[(size_t)E_EDGES * HH];   // per-edge ee, CSR order
__device__ int   g_csr_src[E_EDGES];              // src ids, CSR-by-dst
__device__ int   g_cnt[N_NODES];
__device__ int   g_rowptr[N_NODES + 1];
__device__ int   g_cursor[N_NODES];
__device__ int   g_is64;

// ---------------- helpers ----------------
__device__ __forceinline__ int load_idx(const void* p, long long i) {
    if (g_is64) return (int)((const long long*)p)[i];
    return ((const int*)p)[i];
}

__device__ __forceinline__ float leaky(float v) {
    return v > 0.0f ? v : NEG_SLOPE * v;
}

__device__ __forceinline__ uint32_t f2tf(float f) {
    uint32_t r;
    asm("cvt.rna.tf32.f32 %0, %1;" : "=r"(r) : "f"(f));
    return r;
}

__device__ __forceinline__ void mma_tf32(float* d, const uint32_t* a, const uint32_t* b) {
    asm volatile(
        "mma.sync.aligned.m16n8k8.row.col.f32.tf32.tf32.f32 "
        "{%0,%1,%2,%3}, {%4,%5,%6,%7}, {%8,%9}, {%0,%1,%2,%3};"
        : "+f"(d[0]), "+f"(d[1]), "+f"(d[2]), "+f"(d[3])
        : "r"(a[0]), "r"(a[1]), "r"(a[2]), "r"(a[3]), "r"(b[0]), "r"(b[1]));
}

// ---------------- 0: probe edge_index dtype ----------------
__global__ void probe_kernel(const int* ei32) {
    if (threadIdx.x == 0 && blockIdx.x == 0) {
        int is64 = 1;
        for (int i = 0; i < 64; i++) {
            if (ei32[2 * i + 1] != 0) { is64 = 0; break; }
        }
        g_is64 = is64;
    }
}

// ---------------- 1: GEMM xp = x @ W  (tf32 tensor-core, 128x128x16) --------
#define SA 136
__global__ __launch_bounds__(256)
void gemm_tf32_kernel(const float* __restrict__ A, const float* __restrict__ B) {
    __shared__ uint32_t As[2][16 * SA];
    __shared__ uint32_t Bs[2][16 * SA];

    const int tid  = threadIdx.x;
    const int lane = tid & 31;
    const int wid  = tid >> 5;
    const int wm   = wid >> 2;
    const int wn   = wid & 3;
    const int lm   = lane >> 2;
    const int lk   = lane & 3;

    const int gm0 = blockIdx.y * 128;
    const int bn0 = blockIdx.x * 128;

    const int arow  = tid >> 1;
    const int akoff = (tid & 1) * 8;
    int grow = gm0 + arow;
    if (grow >= N_NODES) grow = N_NODES - 1;
    const float* aptr = A + (size_t)grow * D_IN + akoff;

    const int bkr = tid >> 4;
    const int bcc = (tid & 15) * 4;
    const float* bptr = B + (size_t)bkr * D_OUT + bn0 + bcc;

    float acc[4][4][4];
#pragma unroll
    for (int i = 0; i < 4; i++)
#pragma unroll
        for (int j = 0; j < 4; j++)
#pragma unroll
            for (int r = 0; r < 4; r++) acc[i][j][r] = 0.0f;

    float4 av0, av1, bv0, bv1;

    av0 = *(const float4*)(aptr);
    av1 = *(const float4*)(aptr + 4);
    bv0 = *(const float4*)(bptr);
    bv1 = *(const float4*)(bptr + 64);
    {
        uint32_t* as = As[0];
        as[(akoff + 0) * SA + arow] = f2tf(av0.x);
        as[(akoff + 1) * SA + arow] = f2tf(av0.y);
        as[(akoff + 2) * SA + arow] = f2tf(av0.z);
        as[(akoff + 3) * SA + arow] = f2tf(av0.w);
        as[(akoff + 4) * SA + arow] = f2tf(av1.x);
        as[(akoff + 5) * SA + arow] = f2tf(av1.y);
        as[(akoff + 6) * SA + arow] = f2tf(av1.z);
        as[(akoff + 7) * SA + arow] = f2tf(av1.w);
        uint32_t* bs = Bs[0];
        uint4 p0 = make_uint4(f2tf(bv0.x), f2tf(bv0.y), f2tf(bv0.z), f2tf(bv0.w));
        uint4 p1 = make_uint4(f2tf(bv1.x), f2tf(bv1.y), f2tf(bv1.z), f2tf(bv1.w));
        *(uint4*)&bs[bkr * SA + bcc]      = p0;
        *(uint4*)&bs[bkr * SA + bcc + 64] = p1;
    }
    __syncthreads();

    const int NT = D_IN / 16;
    for (int t = 0; t < NT; t++) {
        if (t + 1 < NT) {
            const int k0 = (t + 1) * 16;
            av0 = *(const float4*)(aptr + k0);
            av1 = *(const float4*)(aptr + k0 + 4);
            bv0 = *(const float4*)(bptr + (size_t)k0 * D_OUT);
            bv1 = *(const float4*)(bptr + (size_t)k0 * D_OUT + 64);
        }

        const uint32_t* as = As[t & 1];
        const uint32_t* bs = Bs[t & 1];
#pragma unroll
        for (int ks = 0; ks < 2; ks++) {
            const int kb = ks * 8;
            uint32_t af[4][4], bf[4][2];
#pragma unroll
            for (int mi = 0; mi < 4; mi++) {
                int r = wm * 64 + mi * 16 + lm;
                af[mi][0] = as[(kb + lk) * SA + r];
                af[mi][1] = as[(kb + lk) * SA + r + 8];
                af[mi][2] = as[(kb + lk + 4) * SA + r];
                af[mi][3] = as[(kb + lk + 4) * SA + r + 8];
            }
#pragma unroll
            for (int ni = 0; ni < 4; ni++) {
                int c = wn * 32 + ni * 8 + lm;
                bf[ni][0] = bs[(kb + lk) * SA + c];
                bf[ni][1] = bs[(kb + lk + 4) * SA + c];
            }
#pragma unroll
            for (int mi = 0; mi < 4; mi++)
#pragma unroll
                for (int ni = 0; ni < 4; ni++)
                    mma_tf32(acc[mi][ni], af[mi], bf[ni]);
        }

        if (t + 1 < NT) {
            uint32_t* asw = As[(t + 1) & 1];
            asw[(akoff + 0) * SA + arow] = f2tf(av0.x);
            asw[(akoff + 1) * SA + arow] = f2tf(av0.y);
            asw[(akoff + 2) * SA + arow] = f2tf(av0.z);
            asw[(akoff + 3) * SA + arow] = f2tf(av0.w);
            asw[(akoff + 4) * SA + arow] = f2tf(av1.x);
            asw[(akoff + 5) * SA + arow] = f2tf(av1.y);
            asw[(akoff + 6) * SA + arow] = f2tf(av1.z);
            asw[(akoff + 7) * SA + arow] = f2tf(av1.w);
            uint32_t* bsw = Bs[(t + 1) & 1];
            uint4 p0 = make_uint4(f2tf(bv0.x), f2tf(bv0.y), f2tf(bv0.z), f2tf(bv0.w));
            uint4 p1 = make_uint4(f2tf(bv1.x), f2tf(bv1.y), f2tf(bv1.z), f2tf(bv1.w));
            *(uint4*)&bsw[bkr * SA + bcc]      = p0;
            *(uint4*)&bsw[bkr * SA + bcc + 64] = p1;
        }
        __syncthreads();
    }

#pragma unroll
    for (int mi = 0; mi < 4; mi++) {
        int row0 = gm0 + wm * 64 + mi * 16 + lm;
#pragma unroll
        for (int ni = 0; ni < 4; ni++) {
            int col = bn0 + wn * 32 + ni * 8 + lk * 2;
            if (row0 < N_NODES)
                *(float2*)&g_xp[(size_t)row0 * D_OUT + col] =
                    make_float2(acc[mi][ni][0], acc[mi][ni][1]);
            if (row0 + 8 < N_NODES)
                *(float2*)&g_xp[(size_t)(row0 + 8) * D_OUT + col] =
                    make_float2(acc[mi][ni][2], acc[mi][ni][3]);
        }
    }
}

// ---------------- 2: per-node attention logits ----------------
__global__ void attn_kernel(const float* __restrict__ att_src,
                            const float* __restrict__ att_dst) {
    const int n = blockIdx.x;
    const int h = threadIdx.x >> 5;
    const int lane = threadIdx.x & 31;
    const float* xrow = g_xp + (size_t)n * D_OUT + h * CC;
    const float* as = att_src + h * CC;
    const float* ad = att_dst + h * CC;
    float s1 = 0.f, s2 = 0.f;
#pragma unroll 4
    for (int c = lane; c < CC; c += 32) {
        float v = xrow[c];
        s1 = fmaf(v, as[c], s1);
        s2 = fmaf(v, ad[c], s2);
    }
#pragma unroll
    for (int o = 16; o; o >>= 1) {
        s1 += __shfl_xor_sync(0xffffffffu, s1, o);
        s2 += __shfl_xor_sync(0xffffffffu, s2, o);
    }
    if (lane == 0) {
        g_asrc[n * HH + h] = s1;
        g_adst[n * HH + h] = s2;
    }
}

// ---------------- 3: CSR build ----------------
__global__ void zero_cnt_kernel() {
    int i = blockIdx.x * 256 + threadIdx.x;
    if (i < N_NODES) g_cnt[i] = 0;
}

__global__ void hist_kernel(const void* __restrict__ ei) {
    long long e = (long long)blockIdx.x * blockDim.x + threadIdx.x;
    if (e >= E_EDGES) return;
    atomicAdd(&g_cnt[load_idx(ei, E_EDGES + e)], 1);
}

__global__ void scan_kernel() {   // single block, 1024 threads
    __shared__ int part[1024];
    const int tid = threadIdx.x;
    const int CH = (N_NODES + 1023) / 1024;   // 25
    const int base = tid * CH;
    int s = 0;
    for (int i = 0; i < CH; i++) {
        int idx = base + i;
        if (idx < N_NODES) s += g_cnt[idx];
    }
    part[tid] = s;
    __syncthreads();
    for (int o = 1; o < 1024; o <<= 1) {
        int v = 0;
        if (tid >= o) v = part[tid - o];
        __syncthreads();
        if (tid >= o) part[tid] += v;
        __syncthreads();
    }
    int run = (tid == 0) ? 0 : part[tid - 1];
    for (int i = 0; i < CH; i++) {
        int idx = base + i;
        if (idx < N_NODES) {
            g_rowptr[idx] = run;
            g_cursor[idx] = run;
            run += g_cnt[idx];
        }
    }
    if (tid == 1023) g_rowptr[N_NODES] = E_EDGES;
}

__global__ void scatter_kernel(const void* __restrict__ ei) {
    long long e = (long long)blockIdx.x * blockDim.x + threadIdx.x;
    if (e >= E_EDGES) return;
    int s = load_idx(ei, e);
    int d = load_idx(ei, E_EDGES + e);
    int pos = atomicAdd(&g_cursor[d], 1);
    g_csr_src[pos] = s;
}

// ---------------- 4: per-dst softmax scalars ----------------
__global__ void softmax_kernel() {
    int d = blockIdx.x * 256 + threadIdx.x;
    if (d >= N_NODES) return;
    float4 ad = *(const float4*)&g_adst[d * HH];
    float4 sf = *(const float4*)&g_asrc[d * HH];
    float m0 = leaky(sf.x + ad.x), m1 = leaky(sf.y + ad.y);
    float m2 = leaky(sf.z + ad.z), m3 = leaky(sf.w + ad.w);
    const int beg = g_rowptr[d], end = g_rowptr[d + 1];
    for (int j = beg; j < end; j++) {
        int s = g_csr_src[j];
        float4 as = *(const float4*)&g_asrc[s * HH];
        m0 = fmaxf(m0, leaky(as.x + ad.x));
        m1 = fmaxf(m1, leaky(as.y + ad.y));
        m2 = fmaxf(m2, leaky(as.z + ad.z));
        m3 = fmaxf(m3, leaky(as.w + ad.w));
    }
    float z0 = expf(leaky(sf.x + ad.x) - m0);
    float z1 = expf(leaky(sf.y + ad.y) - m1);
    float z2 = expf(leaky(sf.z + ad.z) - m2);
    float z3 = expf(leaky(sf.w + ad.w) - m3);
    *(float4*)&g_eself[d * HH] = make_float4(z0, z1, z2, z3);
    for (int j = beg; j < end; j++) {
        int s = g_csr_src[j];
        float4 as = *(const float4*)&g_asrc[s * HH];
        float e0 = expf(leaky(as.x + ad.x) - m0);
        float e1 = expf(leaky(as.y + ad.y) - m1);
        float e2 = expf(leaky(as.z + ad.z) - m2);
        float e3 = expf(leaky(as.w + ad.w) - m3);
        *(float4*)&g_alpha[(size_t)j * HH] = make_float4(e0, e1, e2, e3);
        z0 += e0; z1 += e1; z2 += e2; z3 += e3;
    }
    *(float4*)&g_z[d * HH] = make_float4(z0, z1, z2, z3);
}

// ---------------- 5: warp-per-(dst, half) gather aggregation ----------------
// Each warp handles 512 contiguous cols (2 heads) of one destination row.
__global__ __launch_bounds__(256)
void agg_kernel(float* __restrict__ out, const float* __restrict__ bias) {
    const int w = blockIdx.x * 8 + (threadIdx.x >> 5);
    const int d = w >> 1;
    const int half = w & 1;
    const int lane = threadIdx.x & 31;
    if (d >= N_NODES) return;

    const int col0 = half * 512;                   // covers heads 2*half, 2*half+1
    const int hb = half * 2;

    float2 es = *(const float2*)&g_eself[d * HH + hb];
    float wh[2] = {es.x, es.y};

    float4 acc[4];
    const float* xd = g_xp + (size_t)d * D_OUT + col0;
#pragma unroll
    for (int q = 0; q < 4; q++) {
        const int off = q * 128 + lane * 4;
        float4 v = *(const float4*)(xd + off);
        float wt = wh[q >> 1];
        acc[q] = make_float4(v.x * wt, v.y * wt, v.z * wt, v.w * wt);
    }

    const int beg = g_rowptr[d], end = g_rowptr[d + 1];
    for (int j = beg; j < end; j++) {
        int s = g_csr_src[j];
        float2 a2 = *(const float2*)&g_alpha[(size_t)j * HH + hb];
        float aw[2] = {a2.x, a2.y};
        const float* xs = g_xp + (size_t)s * D_OUT + col0;
#pragma unroll
        for (int q = 0; q < 4; q++) {
            const int off = q * 128 + lane * 4;
            float4 v = *(const float4*)(xs + off);
            float wt = aw[q >> 1];
            acc[q].x = fmaf(v.x, wt, acc[q].x);
            acc[q].y = fmaf(v.y, wt, acc[q].y);
            acc[q].z = fmaf(v.z, wt, acc[q].z);
            acc[q].w = fmaf(v.w, wt, acc[q].w);
        }
    }

    float2 z2 = *(const float2*)&g_z[d * HH + hb];
    float rz[2] = {1.0f / z2.x, 1.0f / z2.y};
    float* orow = out + (size_t)d * D_OUT + col0;
#pragma unroll
    for (int q = 0; q < 4; q++) {
        const int off = q * 128 + lane * 4;
        float4 b4 = *(const float4*)(bias + col0 + off);
        float r = rz[q >> 1];
        float4 o;
        o.x = fmaf(acc[q].x, r, b4.x);
        o.y = fmaf(acc[q].y, r, b4.y);
        o.z = fmaf(acc[q].z, r, b4.z);
        o.w = fmaf(acc[q].w, r, b4.w);
        o.x = o.x > 0.f ? o.x : 0.f;
        o.y = o.y > 0.f ? o.y : 0.f;
        o.z = o.z > 0.f ? o.z : 0.f;
        o.w = o.w > 0.f ? o.w : 0.f;
        *(float4*)(orow + off) = o;
    }
}

// ---------------- launch ----------------
extern "C" void kernel_launch(void* const* d_in, const int* in_sizes, int n_in,
                              void* d_out, int out_size) {
    const float* x        = (const float*)d_in[0];
    const void*  ei       = d_in[1];
    const float* W        = (const float*)d_in[2];
    const float* att_src  = (const float*)d_in[3];
    const float* att_dst  = (const float*)d_in[4];
    const float* bias     = (const float*)d_in[5];
    float* out = (float*)d_out;

    // one-time side stream + fork/join events (host objects, not device mem)
    static cudaStream_t s_side = nullptr;
    static cudaEvent_t  s_fork = nullptr, s_join = nullptr;
    if (!s_side) {
        cudaStreamCreateWithFlags(&s_side, cudaStreamNonBlocking);
        cudaEventCreateWithFlags(&s_fork, cudaEventDisableTiming);
        cudaEventCreateWithFlags(&s_join, cudaEventDisableTiming);
    }

    // fork: CSR build runs on side stream, concurrent with GEMM on main
    cudaEventRecord(s_fork, 0);
    cudaStreamWaitEvent(s_side, s_fork, 0);

    probe_kernel<<<1, 32, 0, s_side>>>((const int*)ei);
    zero_cnt_kernel<<<(N_NODES + 255) / 256, 256, 0, s_side>>>();
    int eb = (E_EDGES + 255) / 256;
    hist_kernel<<<eb, 256, 0, s_side>>>(ei);
    scan_kernel<<<1, 1024, 0, s_side>>>();
    scatter_kernel<<<eb, 256, 0, s_side>>>(ei);
    cudaEventRecord(s_join, s_side);

    // main stream: GEMM + attention logits
    dim3 ggrid(D_OUT / 128, (N_NODES + 127) / 128);
    gemm_tf32_kernel<<<ggrid, 256>>>(x, W);
    attn_kernel<<<N_NODES, 128>>>(att_src, att_dst);

    // join: softmax needs CSR + logits
    cudaStreamWaitEvent(0, s_join, 0);

    softmax_kernel<<<(N_NODES + 255) / 256, 256>>>();

    agg_kernel<<<(2 * N_NODES + 7) / 8, 256>>>(out, bias);
}

// round 10
// speedup vs baseline: 3.4941x; 1.1275x over previous
#include <cuda_runtime.h>
#include <cuda_fp16.h>
#include <cstdint>

#define N_NODES 25000
#define E_EDGES 400000
#define HH 4
#define CC 256
#define D_IN 1024
#define D_OUT 1024   // H*C
#define NEG_SLOPE 0.2f

// ---------------- scratch (device globals: allocation-free) ----------------
__device__ __half g_xph[(size_t)N_NODES * D_OUT]; // projected features, fp16
__device__ float g_asrc[N_NODES * HH];            // attn logits (atomic acc)
__device__ float g_adst[N_NODES * HH];
__device__ int   g_csr_src[E_EDGES];              // src ids, CSR-by-dst
__device__ int   g_cnt[N_NODES];
__device__ int   g_rowptr[N_NODES + 1];
__device__ int   g_cursor[N_NODES];
__device__ int   g_is64;

// ---------------- helpers ----------------
__device__ __forceinline__ int load_idx(const void* p, long long i) {
    if (g_is64) return (int)((const long long*)p)[i];
    return ((const int*)p)[i];
}

__device__ __forceinline__ float leaky(float v) {
    return v > 0.0f ? v : NEG_SLOPE * v;
}

__device__ __forceinline__ uint32_t f2tf(float f) {
    uint32_t r;
    asm("cvt.rna.tf32.f32 %0, %1;" : "=r"(r) : "f"(f));
    return r;
}

__device__ __forceinline__ void mma_tf32(float* d, const uint32_t* a, const uint32_t* b) {
    asm volatile(
        "mma.sync.aligned.m16n8k8.row.col.f32.tf32.tf32.f32 "
        "{%0,%1,%2,%3}, {%4,%5,%6,%7}, {%8,%9}, {%0,%1,%2,%3};"
        : "+f"(d[0]), "+f"(d[1]), "+f"(d[2]), "+f"(d[3])
        : "r"(a[0]), "r"(a[1]), "r"(a[2]), "r"(a[3]), "r"(b[0]), "r"(b[1]));
}

// ---------------- 0: probe edge_index dtype ----------------
__global__ void probe_kernel(const int* ei32) {
    if (threadIdx.x == 0 && blockIdx.x == 0) {
        int is64 = 1;
        for (int i = 0; i < 64; i++) {
            if (ei32[2 * i + 1] != 0) { is64 = 0; break; }
        }
        g_is64 = is64;
    }
}

// ---------------- zero attn accumulators (atomic targets) ----------------
__global__ void zero_attn_kernel() {
    int i = blockIdx.x * 256 + threadIdx.x;
    if (i < N_NODES * HH) { g_asrc[i] = 0.0f; g_adst[i] = 0.0f; }
}

// ---------------- 1: GEMM xp = x @ W (tf32) + fused attn logits + fp16 out --
#define SA 136
__global__ __launch_bounds__(256)
void gemm_tf32_kernel(const float* __restrict__ A, const float* __restrict__ B,
                      const float* __restrict__ att_src,
                      const float* __restrict__ att_dst) {
    __shared__ uint32_t As[2][16 * SA];
    __shared__ uint32_t Bs[2][16 * SA];

    const int tid  = threadIdx.x;
    const int lane = tid & 31;
    const int wid  = tid >> 5;
    const int wm   = wid >> 2;
    const int wn   = wid & 3;
    const int lm   = lane >> 2;
    const int lk   = lane & 3;

    const int gm0 = blockIdx.y * 128;
    const int bn0 = blockIdx.x * 128;

    const int arow  = tid >> 1;
    const int akoff = (tid & 1) * 8;
    int grow = gm0 + arow;
    if (grow >= N_NODES) grow = N_NODES - 1;
    const float* aptr = A + (size_t)grow * D_IN + akoff;

    const int bkr = tid >> 4;
    const int bcc = (tid & 15) * 4;
    const float* bptr = B + (size_t)bkr * D_OUT + bn0 + bcc;

    float acc[4][4][4];
#pragma unroll
    for (int i = 0; i < 4; i++)
#pragma unroll
        for (int j = 0; j < 4; j++)
#pragma unroll
            for (int r = 0; r < 4; r++) acc[i][j][r] = 0.0f;

    float4 av0, av1, bv0, bv1;

    av0 = *(const float4*)(aptr);
    av1 = *(const float4*)(aptr + 4);
    bv0 = *(const float4*)(bptr);
    bv1 = *(const float4*)(bptr + 64);
    {
        uint32_t* as = As[0];
        as[(akoff + 0) * SA + arow] = f2tf(av0.x);
        as[(akoff + 1) * SA + arow] = f2tf(av0.y);
        as[(akoff + 2) * SA + arow] = f2tf(av0.z);
        as[(akoff + 3) * SA + arow] = f2tf(av0.w);
        as[(akoff + 4) * SA + arow] = f2tf(av1.x);
        as[(akoff + 5) * SA + arow] = f2tf(av1.y);
        as[(akoff + 6) * SA + arow] = f2tf(av1.z);
        as[(akoff + 7) * SA + arow] = f2tf(av1.w);
        uint32_t* bs = Bs[0];
        uint4 p0 = make_uint4(f2tf(bv0.x), f2tf(bv0.y), f2tf(bv0.z), f2tf(bv0.w));
        uint4 p1 = make_uint4(f2tf(bv1.x), f2tf(bv1.y), f2tf(bv1.z), f2tf(bv1.w));
        *(uint4*)&bs[bkr * SA + bcc]      = p0;
        *(uint4*)&bs[bkr * SA + bcc + 64] = p1;
    }
    __syncthreads();

    const int NT = D_IN / 16;
    for (int t = 0; t < NT; t++) {
        if (t + 1 < NT) {
            const int k0 = (t + 1) * 16;
            av0 = *(const float4*)(aptr + k0);
            av1 = *(const float4*)(aptr + k0 + 4);
            bv0 = *(const float4*)(bptr + (size_t)k0 * D_OUT);
            bv1 = *(const float4*)(bptr + (size_t)k0 * D_OUT + 64);
        }

        const uint32_t* as = As[t & 1];
        const uint32_t* bs = Bs[t & 1];
#pragma unroll
        for (int ks = 0; ks < 2; ks++) {
            const int kb = ks * 8;
            uint32_t af[4][4], bf[4][2];
#pragma unroll
            for (int mi = 0; mi < 4; mi++) {
                int r = wm * 64 + mi * 16 + lm;
                af[mi][0] = as[(kb + lk) * SA + r];
                af[mi][1] = as[(kb + lk) * SA + r + 8];
                af[mi][2] = as[(kb + lk + 4) * SA + r];
                af[mi][3] = as[(kb + lk + 4) * SA + r + 8];
            }
#pragma unroll
            for (int ni = 0; ni < 4; ni++) {
                int c = wn * 32 + ni * 8 + lm;
                bf[ni][0] = bs[(kb + lk) * SA + c];
                bf[ni][1] = bs[(kb + lk + 4) * SA + c];
            }
#pragma unroll
            for (int mi = 0; mi < 4; mi++)
#pragma unroll
                for (int ni = 0; ni < 4; ni++)
                    mma_tf32(acc[mi][ni], af[mi], bf[ni]);
        }

        if (t + 1 < NT) {
            uint32_t* asw = As[(t + 1) & 1];
            asw[(akoff + 0) * SA + arow] = f2tf(av0.x);
            asw[(akoff + 1) * SA + arow] = f2tf(av0.y);
            asw[(akoff + 2) * SA + arow] = f2tf(av0.z);
            asw[(akoff + 3) * SA + arow] = f2tf(av0.w);
            asw[(akoff + 4) * SA + arow] = f2tf(av1.x);
            asw[(akoff + 5) * SA + arow] = f2tf(av1.y);
            asw[(akoff + 6) * SA + arow] = f2tf(av1.z);
            asw[(akoff + 7) * SA + arow] = f2tf(av1.w);
            uint32_t* bsw = Bs[(t + 1) & 1];
            uint4 p0 = make_uint4(f2tf(bv0.x), f2tf(bv0.y), f2tf(bv0.z), f2tf(bv0.w));
            uint4 p1 = make_uint4(f2tf(bv1.x), f2tf(bv1.y), f2tf(bv1.z), f2tf(bv1.w));
            *(uint4*)&bsw[bkr * SA + bcc]      = p0;
            *(uint4*)&bsw[bkr * SA + bcc + 64] = p1;
        }
        __syncthreads();
    }

    // ---- epilogue: fused attn partial dots + fp16 store ----
    const int head  = bn0 >> 8;          // whole CTA lies in one head
    const int cbase = (bn0 & 255) + wn * 32 + lk * 2;
    float asv[8], adv[8];
#pragma unroll
    for (int ni = 0; ni < 4; ni++) {
#pragma unroll
        for (int c = 0; c < 2; c++) {
            int col = head * 256 + cbase + ni * 8 + c;
            asv[ni * 2 + c] = att_src[col];
            adv[ni * 2 + c] = att_dst[col];
        }
    }

#pragma unroll
    for (int mi = 0; mi < 4; mi++) {
#pragma unroll
        for (int rr = 0; rr < 2; rr++) {
            float ps = 0.f, pd = 0.f;
#pragma unroll
            for (int ni = 0; ni < 4; ni++) {
                float v0 = acc[mi][ni][rr * 2 + 0];
                float v1 = acc[mi][ni][rr * 2 + 1];
                ps = fmaf(v0, asv[ni * 2], fmaf(v1, asv[ni * 2 + 1], ps));
                pd = fmaf(v0, adv[ni * 2], fmaf(v1, adv[ni * 2 + 1], pd));
            }
            ps += __shfl_xor_sync(0xffffffffu, ps, 1);
            ps += __shfl_xor_sync(0xffffffffu, ps, 2);
            pd += __shfl_xor_sync(0xffffffffu, pd, 1);
            pd += __shfl_xor_sync(0xffffffffu, pd, 2);

            const int row = gm0 + wm * 64 + mi * 16 + rr * 8 + lm;
            if (row < N_NODES) {
                if (lk == 0) {
                    atomicAdd(&g_asrc[row * HH + head], ps);
                    atomicAdd(&g_adst[row * HH + head], pd);
                }
#pragma unroll
                for (int ni = 0; ni < 4; ni++) {
                    int col = bn0 + wn * 32 + ni * 8 + lk * 2;
                    __half2 hv = __floats2half2_rn(acc[mi][ni][rr * 2 + 0],
                                                   acc[mi][ni][rr * 2 + 1]);
                    *(__half2*)&g_xph[(size_t)row * D_OUT + col] = hv;
                }
            }
        }
    }
}

// ---------------- 3: CSR build ----------------
__global__ void zero_cnt_kernel() {
    int i = blockIdx.x * 256 + threadIdx.x;
    if (i < N_NODES) g_cnt[i] = 0;
}

__global__ void hist_kernel(const void* __restrict__ ei) {
    long long e = (long long)blockIdx.x * blockDim.x + threadIdx.x;
    if (e >= E_EDGES) return;
    atomicAdd(&g_cnt[load_idx(ei, E_EDGES + e)], 1);
}

__global__ void scan_kernel() {   // single block, 1024 threads
    __shared__ int part[1024];
    const int tid = threadIdx.x;
    const int CH = (N_NODES + 1023) / 1024;   // 25
    const int base = tid * CH;
    int s = 0;
    for (int i = 0; i < CH; i++) {
        int idx = base + i;
        if (idx < N_NODES) s += g_cnt[idx];
    }
    part[tid] = s;
    __syncthreads();
    for (int o = 1; o < 1024; o <<= 1) {
        int v = 0;
        if (tid >= o) v = part[tid - o];
        __syncthreads();
        if (tid >= o) part[tid] += v;
        __syncthreads();
    }
    int run = (tid == 0) ? 0 : part[tid - 1];
    for (int i = 0; i < CH; i++) {
        int idx = base + i;
        if (idx < N_NODES) {
            g_rowptr[idx] = run;
            g_cursor[idx] = run;
            run += g_cnt[idx];
        }
    }
    if (tid == 1023) g_rowptr[N_NODES] = E_EDGES;
}

__global__ void scatter_kernel(const void* __restrict__ ei) {
    long long e = (long long)blockIdx.x * blockDim.x + threadIdx.x;
    if (e >= E_EDGES) return;
    int s = load_idx(ei, e);
    int d = load_idx(ei, E_EDGES + e);
    int pos = atomicAdd(&g_cursor[d], 1);
    g_csr_src[pos] = s;
}

// ---------------- 5: fused softmax + gather aggregation --------------------
// Block = 8 warps = 4 dsts x 2 halves. Warp (d, half) owns 512 cols (2 heads).
// Pass A: warp-parallel max over edges. Pass B (128-edge chunks): lanes
// compute ee -> smem, then serial gather of fp16 rows weighted by ee.
#define ECHUNK 128
__global__ __launch_bounds__(256)
void agg_kernel(float* __restrict__ out, const float* __restrict__ bias) {
    __shared__ float ee_sh[8][ECHUNK][2];

    const int wid  = threadIdx.x >> 5;
    const int lane = threadIdx.x & 31;
    const int d    = blockIdx.x * 4 + (wid >> 1);
    const int half = wid & 1;
    if (d >= N_NODES) return;

    const int hb   = half * 2;
    const int col0 = half * 512;
    const int beg = g_rowptr[d], end = g_rowptr[d + 1];

    const float2 ad = *(const float2*)&g_adst[d * HH + hb];
    const float2 sd = *(const float2*)&g_asrc[d * HH + hb];
    const float self0 = leaky(sd.x + ad.x);
    const float self1 = leaky(sd.y + ad.y);

    // ---- pass A: global max over edges (+ self) ----
    float m0 = self0, m1 = self1;
    for (int j = beg + lane; j < end; j += 32) {
        int s = g_csr_src[j];
        float2 as = *(const float2*)&g_asrc[s * HH + hb];
        m0 = fmaxf(m0, leaky(as.x + ad.x));
        m1 = fmaxf(m1, leaky(as.y + ad.y));
    }
#pragma unroll
    for (int o = 16; o; o >>= 1) {
        m0 = fmaxf(m0, __shfl_xor_sync(0xffffffffu, m0, o));
        m1 = fmaxf(m1, __shfl_xor_sync(0xffffffffu, m1, o));
    }

    // ---- self contribution ----
    const float es0 = expf(self0 - m0);
    const float es1 = expf(self1 - m1);
    float z0 = es0, z1 = es1;           // lane 0..31 identical for self; fix below

    float acc[2][8];
    {
        const __half* xd = g_xph + (size_t)d * D_OUT + col0 + lane * 8;
#pragma unroll
        for (int q = 0; q < 2; q++) {
            uint4 v = *(const uint4*)(xd + q * 256);
            const __half2* h = (const __half2*)&v;
            float w = q ? es1 : es0;
#pragma unroll
            for (int p = 0; p < 4; p++) {
                float2 f = __half22float2(h[p]);
                acc[q][p * 2]     = f.x * w;
                acc[q][p * 2 + 1] = f.y * w;
            }
        }
    }
    // z was initialized with self on EVERY lane; want it counted once.
    if (lane != 0) { z0 = 0.f; z1 = 0.f; }

    // ---- pass B: chunks of ECHUNK edges ----
    for (int c0 = beg; c0 < end; c0 += ECHUNK) {
        const int cend = min(end, c0 + ECHUNK);
        for (int j = c0 + lane; j < cend; j += 32) {
            int s = g_csr_src[j];
            float2 as = *(const float2*)&g_asrc[s * HH + hb];
            float e0 = expf(leaky(as.x + ad.x) - m0);
            float e1 = expf(leaky(as.y + ad.y) - m1);
            ee_sh[wid][j - c0][0] = e0;
            ee_sh[wid][j - c0][1] = e1;
            z0 += e0; z1 += e1;
        }
        __syncwarp();
        for (int j = c0; j < cend; j++) {
            int s = g_csr_src[j];
            float w0 = ee_sh[wid][j - c0][0];
            float w1 = ee_sh[wid][j - c0][1];
            const __half* xs = g_xph + (size_t)s * D_OUT + col0 + lane * 8;
#pragma unroll
            for (int q = 0; q < 2; q++) {
                uint4 v = *(const uint4*)(xs + q * 256);
                const __half2* h = (const __half2*)&v;
                float w = q ? w1 : w0;
#pragma unroll
                for (int p = 0; p < 4; p++) {
                    float2 f = __half22float2(h[p]);
                    acc[q][p * 2]     = fmaf(f.x, w, acc[q][p * 2]);
                    acc[q][p * 2 + 1] = fmaf(f.y, w, acc[q][p * 2 + 1]);
                }
            }
        }
        __syncwarp();
    }

    // ---- z reduce + finalize ----
#pragma unroll
    for (int o = 16; o; o >>= 1) {
        z0 += __shfl_xor_sync(0xffffffffu, z0, o);
        z1 += __shfl_xor_sync(0xffffffffu, z1, o);
    }
    const float rz[2] = {1.0f / z0, 1.0f / z1};

    float* orow = out + (size_t)d * D_OUT + col0 + lane * 8;
    const float* brow = bias + col0 + lane * 8;
#pragma unroll
    for (int q = 0; q < 2; q++) {
        float4 b0 = *(const float4*)(brow + q * 256);
        float4 b1 = *(const float4*)(brow + q * 256 + 4);
        float r = rz[q];
        float4 o0, o1;
        o0.x = fmaf(acc[q][0], r, b0.x); o0.y = fmaf(acc[q][1], r, b0.y);
        o0.z = fmaf(acc[q][2], r, b0.z); o0.w = fmaf(acc[q][3], r, b0.w);
        o1.x = fmaf(acc[q][4], r, b1.x); o1.y = fmaf(acc[q][5], r, b1.y);
        o1.z = fmaf(acc[q][6], r, b1.z); o1.w = fmaf(acc[q][7], r, b1.w);
        o0.x = o0.x > 0.f ? o0.x : 0.f;  o0.y = o0.y > 0.f ? o0.y : 0.f;
        o0.z = o0.z > 0.f ? o0.z : 0.f;  o0.w = o0.w > 0.f ? o0.w : 0.f;
        o1.x = o1.x > 0.f ? o1.x : 0.f;  o1.y = o1.y > 0.f ? o1.y : 0.f;
        o1.z = o1.z > 0.f ? o1.z : 0.f;  o1.w = o1.w > 0.f ? o1.w : 0.f;
        *(float4*)(orow + q * 256)     = o0;
        *(float4*)(orow + q * 256 + 4) = o1;
    }
}

// ---------------- launch ----------------
extern "C" void kernel_launch(void* const* d_in, const int* in_sizes, int n_in,
                              void* d_out, int out_size) {
    const float* x        = (const float*)d_in[0];
    const void*  ei       = d_in[1];
    const float* W        = (const float*)d_in[2];
    const float* att_src  = (const float*)d_in[3];
    const float* att_dst  = (const float*)d_in[4];
    const float* bias     = (const float*)d_in[5];
    float* out = (float*)d_out;

    static cudaStream_t s_side = nullptr;
    static cudaEvent_t  s_fork = nullptr, s_join = nullptr;
    if (!s_side) {
        cudaStreamCreateWithFlags(&s_side, cudaStreamNonBlocking);
        cudaEventCreateWithFlags(&s_fork, cudaEventDisableTiming);
        cudaEventCreateWithFlags(&s_join, cudaEventDisableTiming);
    }

    // fork: CSR build on side stream, concurrent with GEMM
    cudaEventRecord(s_fork, 0);
    cudaStreamWaitEvent(s_side, s_fork, 0);

    probe_kernel<<<1, 32, 0, s_side>>>((const int*)ei);
    zero_cnt_kernel<<<(N_NODES + 255) / 256, 256, 0, s_side>>>();
    int eb = (E_EDGES + 255) / 256;
    hist_kernel<<<eb, 256, 0, s_side>>>(ei);
    scan_kernel<<<1, 1024, 0, s_side>>>();
    scatter_kernel<<<eb, 256, 0, s_side>>>(ei);
    cudaEventRecord(s_join, s_side);

    // main: zero attn accumulators, then GEMM with fused attn + fp16 store
    zero_attn_kernel<<<(N_NODES * HH + 255) / 256, 256>>>();
    dim3 ggrid(D_OUT / 128, (N_NODES + 127) / 128);
    gemm_tf32_kernel<<<ggrid, 256>>>(x, W, att_src, att_dst);

    // join: agg needs CSR + logits
    cudaStreamWaitEvent(0, s_join, 0);

    agg_kernel<<<(N_NODES + 3) / 4, 256>>>(out, bias);
}